// round 14
// baseline (speedup 1.0000x reference)
#include <cuda_runtime.h>
#include <stdint.h>

#define MAX_B     64
#define CAP       4096     // max recorded hits (expected ~5)
#define BM_WORDS  2048     // 65536-bit head bitmap (exact for nn<=65536)
#define NT        256
#define K1_UNROLL 4        // int4 per thread in k1
#define K3_UNROLL 4        // float4 per thread in k3

// Statically zero-initialized. K2 resets g_nhits at its end each call
// (stream-ordered before the next replay's K1), so every replay starts clean.
__device__ int       g_nhits;
__device__ int       g_hit_b[CAP];
__device__ int       g_hit_t[CAP];
__device__ float     g_hit_w[CAP];
__device__ float     g_rowval[MAX_B];     // exact 1/S_b for EVERY row
__device__ int       g_nfix;
__device__ long long g_fix_pos[CAP];      // absolute output position
__device__ float     g_fix_val[CAP];

__device__ __forceinline__ void record_hit(
    int eidx, int h,
    const unsigned int* __restrict__ sbm,
    const int* __restrict__ skeys,
    const int* __restrict__ etype,
    const int* __restrict__ tails,
    const float* __restrict__ w,
    int B, int nn)
{
    if (sbm[(h & 0xFFFF) >> 5] & (1u << (h & 31))) {
        if ((unsigned)h < (unsigned)nn) {
            int key  = (h << 9) | etype[eidx];
            int tail = tails[eidx];
            float wt = w[eidx];
            if ((unsigned)tail < (unsigned)nn) {
                for (int b = 0; b < B; b++) {
                    if (skeys[b] == key) {
                        int idx = atomicAdd(&g_nhits, 1);
                        if (idx < CAP) {
                            g_hit_b[idx] = b;
                            g_hit_t[idx] = tail;
                            g_hit_w[idx] = wt;
                        }
                    }
                }
            }
        }
    }
}

// ---------------------------------------------------------------------------
// K1: streaming scan, 4 int4 per thread (loads batched for MLP), per-block
// smem bitmap prefilter. ~245 blocks — prologue amortized 4x vs R11.
// ---------------------------------------------------------------------------
__global__ void __launch_bounds__(NT, 1)
k1_scan(const int* __restrict__ heads,
        const int* __restrict__ etype,
        const int* __restrict__ tails,
        const float* __restrict__ w,
        const int* __restrict__ batch,
        int E, int B, int nn)
{
    __shared__ unsigned int sbm[BM_WORDS];
    __shared__ int skeys[MAX_B];
    const int tid = threadIdx.x;

    for (int i = tid; i < BM_WORDS; i += NT) sbm[i] = 0u;
    __syncthreads();
    if (tid < B) {
        int h = batch[tid * 96 + 0];        // batch[b,0,0]
        int r = batch[tid * 96 + 2];        // batch[b,0,2]
        skeys[tid] = (h << 9) | r;          // num_rels < 512
        atomicOr(&sbm[(h & 0xFFFF) >> 5], 1u << (h & 31));
    }
    __syncthreads();

    const int4* h4 = reinterpret_cast<const int4*>(heads);
    const int nQuads = E >> 2;
    const int stride = gridDim.x * NT;      // coalesced per unroll step

    for (int q0 = blockIdx.x * NT + tid; q0 < nQuads; q0 += stride * K1_UNROLL) {
        int4 v[K1_UNROLL];
        int  qi[K1_UNROLL];
        bool ok[K1_UNROLL];
        #pragma unroll
        for (int k = 0; k < K1_UNROLL; k++) {
            qi[k] = q0 + k * stride;
            ok[k] = qi[k] < nQuads;
            if (ok[k]) v[k] = h4[qi[k]];    // 4 independent LDG.128 in flight
        }
        #pragma unroll
        for (int k = 0; k < K1_UNROLL; k++) {
            if (ok[k]) {
                int eb = qi[k] << 2;
                record_hit(eb + 0, v[k].x, sbm, skeys, etype, tails, w, B, nn);
                record_hit(eb + 1, v[k].y, sbm, skeys, etype, tails, w, B, nn);
                record_hit(eb + 2, v[k].z, sbm, skeys, etype, tails, w, B, nn);
                record_hit(eb + 3, v[k].w, sbm, skeys, etype, tails, w, B, nn);
            }
        }
    }
    if (blockIdx.x == 0 && tid < (E & 3)) {
        int eidx = (nQuads << 2) + tid;
        record_hit(eidx, heads[eidx], sbm, skeys, etype, tails, w, B, nn);
    }
}

// ---------------------------------------------------------------------------
// K2: single tiny block. Dedupe hits, compute 1/S_b for every row, emit
// point-fixup list, reset the hit counter for the next graph replay.
// ---------------------------------------------------------------------------
__global__ void __launch_bounds__(NT, 1)
k2_aggregate(int B, int nn)
{
    __shared__ float sadj[MAX_B];
    __shared__ int   snf;
    const int tid = threadIdx.x;

    for (int i = tid; i < MAX_B; i += NT) sadj[i] = 0.0f;
    if (tid == 0) snf = 0;
    __syncthreads();

    int n = g_nhits; if (n > CAP) n = CAP;
    for (int i = tid; i < n; i += NT) {
        int b = g_hit_b[i], t = g_hit_t[i];
        float v = g_hit_w[i];
        bool owner = true;
        for (int j = 0; j < n; j++) {
            if (j == i) continue;
            if (g_hit_b[j] == b && g_hit_t[j] == t) {
                if (j < i) { owner = false; break; }
                v += g_hit_w[j];
            }
        }
        if (owner) atomicAdd(&sadj[b], __expf(v) - 1.0f);
    }
    __syncthreads();

    if (tid < B) g_rowval[tid] = 1.0f / ((float)nn + sadj[tid]);
    __syncthreads();

    for (int i = tid; i < n; i += NT) {
        int b = g_hit_b[i], t = g_hit_t[i];
        float v = g_hit_w[i];
        bool owner = true;
        for (int j = 0; j < n; j++) {
            if (j == i) continue;
            if (g_hit_b[j] == b && g_hit_t[j] == t) {
                if (j < i) { owner = false; break; }
                v += g_hit_w[j];
            }
        }
        if (owner) {
            int k = atomicAdd(&snf, 1);
            if (k < CAP) {
                g_fix_pos[k] = (long long)b * nn + t;
                g_fix_val[k] = __expf(v) / ((float)nn + sadj[b]);
            }
        }
    }
    __syncthreads();
    if (tid == 0) {
        g_nfix  = (snf > CAP) ? CAP : snf;
        g_nhits = 0;                         // clean state for next replay
    }
}

// ---------------------------------------------------------------------------
// K3: streaming fill, 4 float4 per thread; per-block disjoint 16 KB chunk;
// in-chunk point fixups after a block-local sync.
// ---------------------------------------------------------------------------
__global__ void __launch_bounds__(NT, 1)
k3_fill(float* __restrict__ out, int B, int nn, int out_size)
{
    __shared__ float srow[MAX_B];
    const int tid = threadIdx.x;
    if (tid < B) srow[tid] = g_rowval[tid];
    __syncthreads();

    const long long lim = (long long)B * nn;
    const int n4 = out_size >> 2;
    const int base = blockIdx.x * (NT * K3_UNROLL);

    if ((nn & 3) == 0) {
        int nn4 = nn >> 2;
        #pragma unroll
        for (int j = 0; j < K3_UNROLL; j++) {
            int i4 = base + j * NT + tid;
            if (i4 < n4) {
                int r = i4 / nn4;
                float v = (r < B) ? srow[r] : 0.0f;
                reinterpret_cast<float4*>(out)[i4] = make_float4(v, v, v, v);
            }
        }
    } else {
        #pragma unroll
        for (int j = 0; j < K3_UNROLL; j++) {
            int i4 = base + j * NT + tid;
            if (i4 < n4) {
                long long pos = (long long)i4 << 2;
                #pragma unroll
                for (int c = 0; c < 4; c++) {
                    long long p = pos + c;
                    out[p] = (p < lim) ? srow[(int)(p / nn)] : 0.0f;
                }
            }
        }
    }
    const bool lastBlk = (blockIdx.x == gridDim.x - 1);
    if (lastBlk) {
        for (int p = (n4 << 2) + tid; p < out_size; p += NT)
            out[p] = ((long long)p < lim) ? srow[(int)((long long)p / nn)] : 0.0f;
    }
    __syncthreads();

    // point fixups inside this block's chunk (disjoint across blocks)
    {
        long long clo = (long long)base << 2;
        long long chi = lastBlk ? (long long)out_size
                                : ((long long)(base + NT * K3_UNROLL) << 2);
        if (chi > out_size) chi = out_size;
        int nf = g_nfix; if (nf > CAP) nf = CAP;
        for (int i = tid; i < nf; i += NT) {
            long long p = g_fix_pos[i];
            if (p >= clo && p < chi) out[p] = g_fix_val[i];
        }
    }
}

extern "C" void kernel_launch(void* const* d_in, const int* in_sizes, int n_in,
                              void* d_out, int out_size) {
    // ---- Identify inputs by SIZE SIGNATURE (ordering-invariant) ----
    int iEI = 0, maxSz = 0;
    for (int i = 0; i < n_in; i++)
        if (in_sizes[i] > maxSz) { maxSz = in_sizes[i]; iEI = i; }
    int E = maxSz / 2;

    int iB = -1, iT = -1, iW = -1;
    for (int i = 0; i < n_in; i++) {
        if (i == iEI) continue;
        int s = in_sizes[i];
        if (s == E)                               { if (iT < 0) iT = i; else iW = i; }
        else if (s > 1 && (s % 96) == 0 && iB < 0) iB = i;
    }

    const int*   edge_index = (const int*)d_in[iEI];
    const int*   edge_type  = (const int*)d_in[iT];
    const int*   batch      = (const int*)d_in[iB];
    const float* edge_w     = (const float*)d_in[iW];

    int B  = in_sizes[iB] / 96;       // 64
    if (B > MAX_B) B = MAX_B;
    int nn = out_size / B;            // 50000
    const int* heads = edge_index;
    const int* tails = edge_index + E;

    // K1: streaming scan (4 int4 per thread)
    int nQuads = E >> 2;
    int g1 = (nQuads + NT * K1_UNROLL - 1) / (NT * K1_UNROLL);
    if (g1 < 1) g1 = 1;
    k1_scan<<<g1, NT>>>(heads, edge_type, tails, edge_w, batch, E, B, nn);

    // K2: tiny aggregation
    k2_aggregate<<<1, NT>>>(B, nn);

    // K3: streaming fill + in-chunk fixups (4 float4 per thread)
    int n4 = out_size >> 2;
    int g3 = (n4 + NT * K3_UNROLL - 1) / (NT * K3_UNROLL);
    if (g3 < 1) g3 = 1;
    k3_fill<<<g3, NT>>>((float*)d_out, B, nn, out_size);
}

// round 15
// speedup vs baseline: 1.7614x; 1.7614x over previous
#include <cuda_runtime.h>
#include <stdint.h>

#define MAX_B        64
#define CAP          4096    // max recorded hits (expected ~5)
#define BM_WORDS_MAX 32768   // exact bitmap, supports nn <= 1,048,576
#define BLOOM_WORDS  64      // 2048-bit coarse bloom (256 B)
#define NT           256
#define K3_UNROLL    2       // float4 per thread in k3 (R11-proven)

// Statically zero-initialized. k0 rebuilds bitmap/bloom/keys each call;
// k2 resets g_nhits at its end — every graph replay starts clean.
__device__ unsigned int g_bitmap[BM_WORDS_MAX];
__device__ unsigned int g_bloom[BLOOM_WORDS];
__device__ int          g_keys[MAX_B];
__device__ int          g_nhits;
__device__ int          g_hit_b[CAP];
__device__ int          g_hit_t[CAP];
__device__ float        g_hit_w[CAP];
__device__ float        g_rowval[MAX_B];    // exact 1/S_b for EVERY row
__device__ int          g_nfix;
__device__ long long    g_fix_pos[CAP];
__device__ float        g_fix_val[CAP];

// ---------------------------------------------------------------------------
// K0: one tiny block. Zero exact bitmap + bloom, build keys, set bits.
// ---------------------------------------------------------------------------
__global__ void __launch_bounds__(NT, 1)
k0_prep(const int* __restrict__ batch, int B, int bmWords)
{
    const int tid = threadIdx.x;
    for (int i = tid; i < bmWords; i += NT) g_bitmap[i] = 0u;
    if (tid < BLOOM_WORDS) g_bloom[tid] = 0u;
    __syncthreads();
    if (tid < B) {
        int h = batch[tid * 96 + 0];     // batch[b,0,0]
        int r = batch[tid * 96 + 2];     // batch[b,0,2]
        g_keys[tid] = (h << 9) | r;      // num_rels < 512
        atomicOr(&g_bitmap[h >> 5], 1u << (h & 31));
        atomicOr(&g_bloom[(h >> 5) & (BLOOM_WORDS - 1)], 1u << (h & 31));
    }
}

// ---------------------------------------------------------------------------
// K1: streaming scan, 1 int4 per thread (R11-proven shape, 977 blocks).
// Prologue: 2 coalesced loads (bloom word + key) for tid<64, one sync.
// Probe chain: smem bloom (LDS) -> exact global bitmap (L1) -> key compare.
// ---------------------------------------------------------------------------
__device__ __forceinline__ void check_edge(
    int eidx, int h,
    const unsigned int* __restrict__ sbloom,
    const int* __restrict__ skeys,
    const int* __restrict__ etype,
    const int* __restrict__ tails,
    const float* __restrict__ w,
    int B, int nn)
{
    if (sbloom[(h >> 5) & (BLOOM_WORDS - 1)] & (1u << (h & 31))) {      // ~3% pass
        if ((unsigned)h < (unsigned)nn &&
            (__ldg(&g_bitmap[h >> 5]) & (1u << (h & 31)))) {             // exact
            int key  = (h << 9) | etype[eidx];
            int tail = tails[eidx];
            float wt = w[eidx];
            if ((unsigned)tail < (unsigned)nn) {
                for (int b = 0; b < B; b++) {
                    if (skeys[b] == key) {
                        int idx = atomicAdd(&g_nhits, 1);
                        if (idx < CAP) {
                            g_hit_b[idx] = b;
                            g_hit_t[idx] = tail;
                            g_hit_w[idx] = wt;
                        }
                    }
                }
            }
        }
    }
}

__global__ void __launch_bounds__(NT, 1)
k1_scan(const int* __restrict__ heads,
        const int* __restrict__ etype,
        const int* __restrict__ tails,
        const float* __restrict__ w,
        int E, int B, int nn)
{
    __shared__ unsigned int sbloom[BLOOM_WORDS];
    __shared__ int skeys[MAX_B];
    const int tid = threadIdx.x;

    if (tid < BLOOM_WORDS) sbloom[tid] = g_bloom[tid];
    if (tid < MAX_B) skeys[tid] = (tid < B) ? g_keys[tid] : 0x7FFFFFFF;
    __syncthreads();

    const int4* h4 = reinterpret_cast<const int4*>(heads);
    const int nQuads = E >> 2;
    const int q = blockIdx.x * NT + tid;
    if (q < nQuads) {
        int4 hh = h4[q];
        int eb = q << 2;
        check_edge(eb + 0, hh.x, sbloom, skeys, etype, tails, w, B, nn);
        check_edge(eb + 1, hh.y, sbloom, skeys, etype, tails, w, B, nn);
        check_edge(eb + 2, hh.z, sbloom, skeys, etype, tails, w, B, nn);
        check_edge(eb + 3, hh.w, sbloom, skeys, etype, tails, w, B, nn);
    }
    if (blockIdx.x == 0 && tid < (E & 3)) {
        int eidx = (nQuads << 2) + tid;
        check_edge(eidx, heads[eidx], sbloom, skeys, etype, tails, w, B, nn);
    }
}

// ---------------------------------------------------------------------------
// K2: single tiny block. Dedupe hits, compute 1/S_b per row, emit point
// fixups, reset hit counter for the next graph replay.
// ---------------------------------------------------------------------------
__global__ void __launch_bounds__(NT, 1)
k2_aggregate(int B, int nn)
{
    __shared__ float sadj[MAX_B];
    __shared__ int   snf;
    const int tid = threadIdx.x;

    for (int i = tid; i < MAX_B; i += NT) sadj[i] = 0.0f;
    if (tid == 0) snf = 0;
    __syncthreads();

    int n = g_nhits; if (n > CAP) n = CAP;
    for (int i = tid; i < n; i += NT) {
        int b = g_hit_b[i], t = g_hit_t[i];
        float v = g_hit_w[i];
        bool owner = true;
        for (int j = 0; j < n; j++) {
            if (j == i) continue;
            if (g_hit_b[j] == b && g_hit_t[j] == t) {
                if (j < i) { owner = false; break; }
                v += g_hit_w[j];
            }
        }
        if (owner) atomicAdd(&sadj[b], __expf(v) - 1.0f);
    }
    __syncthreads();

    if (tid < B) g_rowval[tid] = 1.0f / ((float)nn + sadj[tid]);
    __syncthreads();

    for (int i = tid; i < n; i += NT) {
        int b = g_hit_b[i], t = g_hit_t[i];
        float v = g_hit_w[i];
        bool owner = true;
        for (int j = 0; j < n; j++) {
            if (j == i) continue;
            if (g_hit_b[j] == b && g_hit_t[j] == t) {
                if (j < i) { owner = false; break; }
                v += g_hit_w[j];
            }
        }
        if (owner) {
            int k = atomicAdd(&snf, 1);
            if (k < CAP) {
                g_fix_pos[k] = (long long)b * nn + t;
                g_fix_val[k] = __expf(v) / ((float)nn + sadj[b]);
            }
        }
    }
    __syncthreads();
    if (tid == 0) {
        g_nfix  = (snf > CAP) ? CAP : snf;
        g_nhits = 0;                        // clean state for next replay
    }
}

// ---------------------------------------------------------------------------
// K3: streaming fill, 2 float4 per thread (R11-proven); disjoint chunks;
// in-chunk point fixups after a block-local sync.
// ---------------------------------------------------------------------------
__global__ void __launch_bounds__(NT, 1)
k3_fill(float* __restrict__ out, int B, int nn, int out_size)
{
    __shared__ float srow[MAX_B];
    const int tid = threadIdx.x;
    if (tid < B) srow[tid] = g_rowval[tid];
    __syncthreads();

    const long long lim = (long long)B * nn;
    const int n4 = out_size >> 2;
    const int base = blockIdx.x * (NT * K3_UNROLL);

    if ((nn & 3) == 0) {
        int nn4 = nn >> 2;
        #pragma unroll
        for (int j = 0; j < K3_UNROLL; j++) {
            int i4 = base + j * NT + tid;
            if (i4 < n4) {
                int r = i4 / nn4;
                float v = (r < B) ? srow[r] : 0.0f;
                reinterpret_cast<float4*>(out)[i4] = make_float4(v, v, v, v);
            }
        }
    } else {
        #pragma unroll
        for (int j = 0; j < K3_UNROLL; j++) {
            int i4 = base + j * NT + tid;
            if (i4 < n4) {
                long long pos = (long long)i4 << 2;
                #pragma unroll
                for (int c = 0; c < 4; c++) {
                    long long p = pos + c;
                    out[p] = (p < lim) ? srow[(int)(p / nn)] : 0.0f;
                }
            }
        }
    }
    const bool lastBlk = (blockIdx.x == gridDim.x - 1);
    if (lastBlk) {
        for (int p = (n4 << 2) + tid; p < out_size; p += NT)
            out[p] = ((long long)p < lim) ? srow[(int)((long long)p / nn)] : 0.0f;
    }
    __syncthreads();

    {
        long long clo = (long long)base << 2;
        long long chi = lastBlk ? (long long)out_size
                                : ((long long)(base + NT * K3_UNROLL) << 2);
        if (chi > out_size) chi = out_size;
        int nf = g_nfix; if (nf > CAP) nf = CAP;
        for (int i = tid; i < nf; i += NT) {
            long long p = g_fix_pos[i];
            if (p >= clo && p < chi) out[p] = g_fix_val[i];
        }
    }
}

extern "C" void kernel_launch(void* const* d_in, const int* in_sizes, int n_in,
                              void* d_out, int out_size) {
    // ---- Identify inputs by SIZE SIGNATURE (ordering-invariant) ----
    int iEI = 0, maxSz = 0;
    for (int i = 0; i < n_in; i++)
        if (in_sizes[i] > maxSz) { maxSz = in_sizes[i]; iEI = i; }
    int E = maxSz / 2;

    int iB = -1, iT = -1, iW = -1;
    for (int i = 0; i < n_in; i++) {
        if (i == iEI) continue;
        int s = in_sizes[i];
        if (s == E)                               { if (iT < 0) iT = i; else iW = i; }
        else if (s > 1 && (s % 96) == 0 && iB < 0) iB = i;
    }

    const int*   edge_index = (const int*)d_in[iEI];
    const int*   edge_type  = (const int*)d_in[iT];
    const int*   batch      = (const int*)d_in[iB];
    const float* edge_w     = (const float*)d_in[iW];

    int B  = in_sizes[iB] / 96;       // 64
    if (B > MAX_B) B = MAX_B;
    int nn = out_size / B;            // 50000
    const int* heads = edge_index;
    const int* tails = edge_index + E;

    int bmWords = (nn + 31) / 32;
    if (bmWords > BM_WORDS_MAX) bmWords = BM_WORDS_MAX;

    // K0: build bitmap/bloom/keys
    k0_prep<<<1, NT>>>(batch, B, bmWords);

    // K1: streaming scan (1 int4 per thread, R11-proven shape)
    int nQuads = E >> 2;
    int g1 = (nQuads + NT - 1) / NT;
    if (g1 < 1) g1 = 1;
    k1_scan<<<g1, NT>>>(heads, edge_type, tails, edge_w, E, B, nn);

    // K2: tiny aggregation
    k2_aggregate<<<1, NT>>>(B, nn);

    // K3: streaming fill + in-chunk fixups (2 float4 per thread)
    int n4 = out_size >> 2;
    int g3 = (n4 + NT * K3_UNROLL - 1) / (NT * K3_UNROLL);
    if (g3 < 1) g3 = 1;
    k3_fill<<<g3, NT>>>((float*)d_out, B, nn, out_size);
}